// round 1
// baseline (speedup 1.0000x reference)
#include <cuda_runtime.h>

#define N_DIM 8192
#define ROW4 (N_DIM / 4)          // 2048 float4 per row
#define TOTAL4 (N_DIM * ROW4)     // 16,777,216 float4 elements

// Scratch accumulators (allocation-free __device__ globals).
__device__ double g_sumAbsC;
__device__ double g_sumCW;
__device__ double g_sumW;

__global__ void zero_accum_kernel() {
    g_sumAbsC = 0.0;
    g_sumCW   = 0.0;
    g_sumW    = 0.0;
}

__global__ __launch_bounds__(256) void parietal_main_kernel(
    const float*  __restrict__ a,      // [N_DIM] neural activities
    const float4* __restrict__ W4,     // [N_DIM*N_DIM/4] connection matrix
    const float4* __restrict__ Cin4,   // [N_DIM*N_DIM/4] correlation matrix (in)
    float4*       __restrict__ Cout4)  // [N_DIM*N_DIM/4] C (out)
{
    const float decay = 0.9f;
    const float one_minus = 0.1f;

    float sAbs = 0.0f, sCW = 0.0f, sW = 0.0f;

    const int stride = gridDim.x * blockDim.x;
    for (int idx4 = blockIdx.x * blockDim.x + threadIdx.x; idx4 < TOTAL4; idx4 += stride) {
        const int i  = idx4 >> 11;      // row (ROW4 = 2048 = 1<<11)
        const int j4 = idx4 & 2047;     // float4-column

        const float4 c = Cin4[idx4];
        const float4 w = W4[idx4];
        const float  ai = __ldg(&a[i]);
        const float4 aj = reinterpret_cast<const float4*>(a)[j4];

        // diagonal element falls in this float4 iff i/4 == j4; lane = i&3
        const int diagLane = ((i >> 2) == j4) ? (i & 3) : -1;

        float o0 = (diagLane == 0) ? c.x : fmaf(one_minus * ai, aj.x, decay * c.x);
        float o1 = (diagLane == 1) ? c.y : fmaf(one_minus * ai, aj.y, decay * c.y);
        float o2 = (diagLane == 2) ? c.z : fmaf(one_minus * ai, aj.z, decay * c.z);
        float o3 = (diagLane == 3) ? c.w : fmaf(one_minus * ai, aj.w, decay * c.w);

        const float a0 = fabsf(o0), a1 = fabsf(o1), a2 = fabsf(o2), a3 = fabsf(o3);

        sAbs += (a0 + a1) + (a2 + a3);
        sW   += (w.x + w.y) + (w.z + w.w);
        sCW  += (a0 * w.x + a1 * w.y) + (a2 * w.z + a3 * w.w);

        Cout4[idx4] = make_float4(o0, o1, o2, o3);
    }

    // Warp reduction
    #pragma unroll
    for (int off = 16; off > 0; off >>= 1) {
        sAbs += __shfl_down_sync(0xFFFFFFFFu, sAbs, off);
        sCW  += __shfl_down_sync(0xFFFFFFFFu, sCW,  off);
        sW   += __shfl_down_sync(0xFFFFFFFFu, sW,   off);
    }

    __shared__ float redAbs[8], redCW[8], redW[8];
    const int lane = threadIdx.x & 31;
    const int wid  = threadIdx.x >> 5;
    if (lane == 0) { redAbs[wid] = sAbs; redCW[wid] = sCW; redW[wid] = sW; }
    __syncthreads();

    if (wid == 0) {
        float bAbs = (lane < 8) ? redAbs[lane] : 0.0f;
        float bCW  = (lane < 8) ? redCW[lane]  : 0.0f;
        float bW   = (lane < 8) ? redW[lane]   : 0.0f;
        #pragma unroll
        for (int off = 4; off > 0; off >>= 1) {
            bAbs += __shfl_down_sync(0xFFFFFFFFu, bAbs, off);
            bCW  += __shfl_down_sync(0xFFFFFFFFu, bCW,  off);
            bW   += __shfl_down_sync(0xFFFFFFFFu, bW,   off);
        }
        if (lane == 0) {
            atomicAdd(&g_sumAbsC, (double)bAbs);
            atomicAdd(&g_sumCW,   (double)bCW);
            atomicAdd(&g_sumW,    (double)bW);
        }
    }
}

__global__ void finalize_kernel(
    const float* __restrict__ coh_in,     // [1] coherence_strength
    const float* __restrict__ integ_in,   // [1] integration_measure
    float*       __restrict__ out_tail)   // -> d_out + N*N (3 floats)
{
    const double corr_sum = g_sumAbsC;
    const double wsum     = g_sumW;

    const double n_conn = (double)N_DIM * (double)(N_DIM - 1);
    float coherence = 0.9f * coh_in[0] + 0.1f * (float)(corr_sum / n_conn);

    float integration;
    if (wsum > 0.0) {
        const float integ_raw = (float)(g_sumCW / wsum);
        integration = 0.9f * integ_in[0] + 0.1f * integ_raw;
    } else {
        integration = integ_in[0];
    }

    const double n_total = (double)N_DIM * (double)N_DIM;
    float synchrony = (float)(corr_sum / n_total);

    out_tail[0] = coherence;
    out_tail[1] = integration;
    out_tail[2] = synchrony;
}

extern "C" void kernel_launch(void* const* d_in, const int* in_sizes, int n_in,
                              void* d_out, int out_size) {
    const float* a     = (const float*)d_in[0];   // neural_activities [8192]
    const float* W     = (const float*)d_in[1];   // connection_matrix [8192*8192]
    const float* Cin   = (const float*)d_in[2];   // correlation_matrix [8192*8192]
    const float* coh   = (const float*)d_in[3];   // coherence_strength [1]
    const float* integ = (const float*)d_in[4];   // integration_measure [1]

    float* out = (float*)d_out;   // [N*N] C, then coherence, integration, synchrony

    zero_accum_kernel<<<1, 1>>>();
    parietal_main_kernel<<<2048, 256>>>(
        a,
        (const float4*)W,
        (const float4*)Cin,
        (float4*)out);
    finalize_kernel<<<1, 1>>>(coh, integ, out + (size_t)N_DIM * N_DIM);
}